// round 10
// baseline (speedup 1.0000x reference)
#include <cuda_runtime.h>
#include <cuda_fp16.h>
#include <cstdint>

#define B_    4
#define CIN   256
#define HH    64
#define WW    64
#define COUT  256
#define K2    9
#define NPIX  4096
#define NCHUNK 36               // 4 ci64-chunks * 9 k2, order: c64 outer, k2 inner
#define RPITCH 160              // bytes per smem row (64 halves data + pad): conflict-free LDS.64

// ---------------- scratch ----------------
__device__ __align__(16) __half   g_xh[B_ * NPIX * CIN];     // x NHWC fp16
__device__ __align__(16) __half   g_wh[NCHUNK * 256 * 64];   // W fp16: [ch][co256][k64 permuted]
__device__ __align__(16) int4     g_sidx[B_ * K2 * NPIX];    // corner bases in uint4 units (pix*32)
__device__ __align__(16) float4   g_swt [B_ * K2 * NPIX];
__device__ __align__(16) float2   g_part[B_ * 32 * 64];      // GN partials [(b*32+g)*64 + tile]

__device__ __forceinline__ uint32_t smem_u32(const void* p) {
    uint32_t a;
    asm("{ .reg .u64 t; cvta.to.shared.u64 t, %1; cvt.u32.u64 %0, t; }" : "=r"(a) : "l"(p));
    return a;
}
__device__ __forceinline__ void mma_f16(float* c, uint32_t a0, uint32_t a1,
                                        uint32_t a2, uint32_t a3,
                                        uint32_t b0, uint32_t b1) {
    asm volatile("mma.sync.aligned.m16n8k16.row.col.f32.f16.f16.f32 "
        "{%0,%1,%2,%3}, {%4,%5,%6,%7}, {%8,%9}, {%0,%1,%2,%3};"
        : "+f"(c[0]), "+f"(c[1]), "+f"(c[2]), "+f"(c[3])
        : "r"(a0), "r"(a1), "r"(a2), "r"(a3), "r"(b0), "r"(b1));
}

// ---------------------------------------------------------------------------
// Prep 1: x NCHW -> NHWC fp16
__global__ void k_prep_x(const float* __restrict__ x) {
    __shared__ float tile[32][33];
    int b = blockIdx.z, p0 = blockIdx.x * 32, c0 = blockIdx.y * 32;
    int tx = threadIdx.x, ty = threadIdx.y;
#pragma unroll
    for (int i = ty; i < 32; i += 8)
        tile[i][tx] = x[(b * CIN + c0 + i) * NPIX + p0 + tx];
    __syncthreads();
#pragma unroll
    for (int i = ty; i < 32; i += 8)
        g_xh[(b * NPIX + p0 + i) * CIN + c0 + tx] = __float2half_rn(tile[tx][i]);
}

// Prep 2: W -> fp16 chunks [ch = c64*9 + k2][co][k64], k permuted within each
// group of 16: pos 4t+{0,1,2,3} <- k {2t, 2t+1, 2t+8, 2t+9}. A uses the same
// permutation, so the GEMM is unchanged while each fragment is one LDS.64.
__global__ void k_prep_w(const float* __restrict__ w) {
    int ch  = blockIdx.x;
    int c64 = ch / 9, k2 = ch - c64 * 9;
    __half* dst = g_wh + ch * 16384;
    for (int e = threadIdx.x; e < 16384; e += 256) {
        int co = e >> 6, p = e & 63;
        int gp = p >> 4, r = p & 15, t = r >> 2, u = r & 3;
        int k = gp * 16 + 2 * t + (u & 1) + ((u & 2) ? 8 : 0);
        float v = w[(co * CIN + c64 * 64 + k) * K2 + k2];
        dst[co * 64 + p] = __float2half_rn(v);
    }
}

// Prep 3: sampling params (corner bases in uint4 units, folded weights)
__global__ void k_prep_params(const float* __restrict__ offset,
                              const float* __restrict__ mask) {
    int t = blockIdx.x * blockDim.x + threadIdx.x;
    int b  = t / (K2 * NPIX);
    int r  = t - b * (K2 * NPIX);
    int k2 = r >> 12;
    int p  = r & (NPIX - 1);
    int ho = p >> 6, wo = p & 63;
    int ky = k2 / 3, kx = k2 - ky * 3;

    float dy_off = offset[(b * 2 * K2 + 2 * k2    ) * NPIX + p];
    float dx_off = offset[(b * 2 * K2 + 2 * k2 + 1) * NPIX + p];
    float m      = mask  [(b * K2 + k2) * NPIX + p];

    float yf = (float)(ky + ho - 1) + dy_off;
    float xf = (float)(kx + wo - 1) + dx_off;
    float y0f = floorf(yf), x0f = floorf(xf);
    float dy = yf - y0f, dx = xf - x0f;
    int y0 = (int)y0f, x0 = (int)x0f;
    int y1 = y0 + 1,   x1 = x0 + 1;

    float w00 = (1.f - dy) * (1.f - dx) * m;
    float w01 = (1.f - dy) * dx * m;
    float w10 = dy * (1.f - dx) * m;
    float w11 = dy * dx * m;
    bool vy0 = (y0 >= 0) & (y0 < HH), vy1 = (y1 >= 0) & (y1 < HH);
    bool vx0 = (x0 >= 0) & (x0 < WW), vx1 = (x1 >= 0) & (x1 < WW);
    if (!(vy0 & vx0)) w00 = 0.f;
    if (!(vy0 & vx1)) w01 = 0.f;
    if (!(vy1 & vx0)) w10 = 0.f;
    if (!(vy1 & vx1)) w11 = 0.f;

    int y0c = min(max(y0, 0), HH - 1), y1c = min(max(y1, 0), HH - 1);
    int x0c = min(max(x0, 0), WW - 1), x1c = min(max(x1, 0), WW - 1);
    int base = b * NPIX;
    g_sidx[t] = make_int4((base + y0c * WW + x0c) * 32,
                          (base + y0c * WW + x1c) * 32,
                          (base + y1c * WW + x0c) * 32,
                          (base + y1c * WW + x1c) * 32);
    g_swt[t] = make_float4(w00, w01, w10, w11);
}

// ---------------------------------------------------------------------------
// Main: fp16 m16n8k16 implicit GEMM, fp32 accumulate + fused GN partial stats.
// CTA: 64px x 256co, K=2304 in 36 chunks of 64 (c64 outer, k2 inner).
// grid 256, block 256 (8 warps), warp tile 32px x 64co, 2 CTAs/SM.
// Corner-granular pipeline: one bilinear corner (8 regs) in flight at a time,
// interleaved between the 4 ks MMA sub-sections -> gather latency hidden with
// no register spills.
// ---------------------------------------------------------------------------
// bytes: A0 0 | A1 10240 | W0 20480 | W1 61440 | sB 102400 | sP 103424 | end 103936
#define SMEM_DYN 103936

__global__ __launch_bounds__(256, 2)
void k_conv(const float* __restrict__ bias, float* __restrict__ out) {
    extern __shared__ char dsm[];
    char*   A_s[2] = { dsm,         dsm + 10240 };
    char*   W_s[2] = { dsm + 20480, dsm + 61440 };
    float*  sB = (float*)(dsm + 102400);
    float2* sP = (float2*)(dsm + 103424);        // [2 wm][32 groups]

    int tid  = threadIdx.x;
    int b    = blockIdx.x >> 6;
    int tile = blockIdx.x & 63;
    int p0   = tile * 64;
    int warp = tid >> 5, lane = tid & 31;

    sB[tid] = bias[tid];

    // ---- per-thread mappings ----
    int ty = lane >> 2, tk = lane & 3;        // mma frag coords
    int wm = warp >> 2, wn = warp & 3;        // warp tile: px wm*32, co wn*64
    int pl_b = tid >> 2, q_b = tid & 3;       // A-build: pixel, k-group-of-16
    const uint4* Xh = (const uint4*)g_xh;

    float acc[2][8][4];
#pragma unroll
    for (int i = 0; i < 2; i++)
#pragma unroll
        for (int j = 0; j < 8; j++)
#pragma unroll
            for (int qq = 0; qq < 4; qq++) acc[i][j][qq] = 0.f;

    // ---- builders ----
    auto build_W = [&](int ch, int s) {
        const char* src = (const char*)(g_wh + ch * 16384);
        uint32_t dst = smem_u32(W_s[s]);
#pragma unroll
        for (int i = 0; i < 8; i++) {
            int lin = tid + i * 256;             // 0..2047
            int co = lin >> 3, seg = lin & 7;    // 16B segment of 128B row
            uint32_t d = dst + (uint32_t)(co * RPITCH + seg * 16);
            const char* gp = src + (size_t)lin * 16;
            asm volatile("cp.async.cg.shared.global [%0], [%1], 16;" :: "r"(d), "l"(gp));
        }
        asm volatile("cp.async.commit_group;" ::: "memory");
    };
    // Permuted STS of the finished bilinear result v (8 half2).
    auto sts_A = [&](int s, const __half2* v) {
        const uint32_t* vv = (const uint32_t*)v;
        uint4 s1 = make_uint4(vv[0], vv[4], vv[1], vv[5]);
        uint4 s2 = make_uint4(vv[2], vv[6], vv[3], vv[7]);
        uint4* ab = (uint4*)(A_s[s] + pl_b * RPITCH + q_b * 32);
        ab[0] = s1;
        ab[1] = s2;
    };

    // ---- prologue: build chunk 0 (monolithic, one-time) ----
    {
        build_W(0, 0);
        int t = (b * K2 + 0) * NPIX + p0 + pl_b;   // ch 0: c64=0, k2=0
        int4   o  = __ldg(&g_sidx[t]);
        float4 wt = __ldg(&g_swt[t]);
        int cio = 2 * q_b;
        uint4 u[2];
        __half2 v[8];
        u[0] = __ldg(&Xh[o.x + cio]); u[1] = __ldg(&Xh[o.x + cio + 1]);
        {
            __half2 w = __float2half2_rn(wt.x);
            const __half2* h2 = (const __half2*)u;
#pragma unroll
            for (int h = 0; h < 8; h++) v[h] = __hmul2(w, h2[h]);
        }
        u[0] = __ldg(&Xh[o.y + cio]); u[1] = __ldg(&Xh[o.y + cio + 1]);
        {
            __half2 w = __float2half2_rn(wt.y);
            const __half2* h2 = (const __half2*)u;
#pragma unroll
            for (int h = 0; h < 8; h++) v[h] = __hfma2(w, h2[h], v[h]);
        }
        u[0] = __ldg(&Xh[o.z + cio]); u[1] = __ldg(&Xh[o.z + cio + 1]);
        {
            __half2 w = __float2half2_rn(wt.z);
            const __half2* h2 = (const __half2*)u;
#pragma unroll
            for (int h = 0; h < 8; h++) v[h] = __hfma2(w, h2[h], v[h]);
        }
        u[0] = __ldg(&Xh[o.w + cio]); u[1] = __ldg(&Xh[o.w + cio + 1]);
        {
            __half2 w = __float2half2_rn(wt.w);
            const __half2* h2 = (const __half2*)u;
#pragma unroll
            for (int h = 0; h < 8; h++) v[h] = __hfma2(w, h2[h], v[h]);
        }
        sts_A(0, v);
    }
    asm volatile("cp.async.wait_group 0;" ::: "memory");
    __syncthreads();

    for (int ch = 0; ch < NCHUNK; ch++) {
        int s = ch & 1;
        bool has = (ch + 1 < NCHUNK);

        // next-chunk gather state (one corner in flight: u[2]; running sum v)
        int4 o; float4 wt; int cio = 0;
        uint4 u[2];
        __half2 v[8];
        if (has) {
            build_W(ch + 1, s ^ 1);
            int c64 = (ch + 1) / 9, k2 = (ch + 1) - c64 * 9;
            int t = (b * K2 + k2) * NPIX + p0 + pl_b;
            o  = __ldg(&g_sidx[t]);
            wt = __ldg(&g_swt[t]);
            cio = c64 * 8 + 2 * q_b;
            u[0] = __ldg(&Xh[o.x + cio]); u[1] = __ldg(&Xh[o.x + cio + 1]);
        }

        const char* As = A_s[s] + (wm * 32 + ty) * RPITCH + tk * 8;
        const char* Ws = W_s[s] + (wn * 64 + ty) * RPITCH + tk * 8;
        auto mma_step = [&](int ks) {
            uint2 alo[2], ahi[2], bv[8];
#pragma unroll
            for (int i = 0; i < 2; i++) {
                alo[i] = *(const uint2*)(As + i * (16 * RPITCH) + ks * 32);
                ahi[i] = *(const uint2*)(As + i * (16 * RPITCH) + 8 * RPITCH + ks * 32);
            }
#pragma unroll
            for (int j = 0; j < 8; j++)
                bv[j] = *(const uint2*)(Ws + j * (8 * RPITCH) + ks * 32);
#pragma unroll
            for (int i = 0; i < 2; i++)
#pragma unroll
                for (int j = 0; j < 8; j++)
                    mma_f16(acc[i][j], alo[i].x, ahi[i].x, alo[i].y, ahi[i].y,
                            bv[j].x, bv[j].y);
        };

        mma_step(0);
        if (has) {   // corner0 done -> fold; launch corner1
            __half2 w = __float2half2_rn(wt.x);
            const __half2* h2 = (const __half2*)u;
#pragma unroll
            for (int h = 0; h < 8; h++) v[h] = __hmul2(w, h2[h]);
            u[0] = __ldg(&Xh[o.y + cio]); u[1] = __ldg(&Xh[o.y + cio + 1]);
        }
        mma_step(1);
        if (has) {
            __half2 w = __float2half2_rn(wt.y);
            const __half2* h2 = (const __half2*)u;
#pragma unroll
            for (int h = 0; h < 8; h++) v[h] = __hfma2(w, h2[h], v[h]);
            u[0] = __ldg(&Xh[o.z + cio]); u[1] = __ldg(&Xh[o.z + cio + 1]);
        }
        mma_step(2);
        if (has) {
            __half2 w = __float2half2_rn(wt.z);
            const __half2* h2 = (const __half2*)u;
#pragma unroll
            for (int h = 0; h < 8; h++) v[h] = __hfma2(w, h2[h], v[h]);
            u[0] = __ldg(&Xh[o.w + cio]); u[1] = __ldg(&Xh[o.w + cio + 1]);
        }
        mma_step(3);
        if (has) {
            __half2 w = __float2half2_rn(wt.w);
            const __half2* h2 = (const __half2*)u;
#pragma unroll
            for (int h = 0; h < 8; h++) v[h] = __hfma2(w, h2[h], v[h]);
            sts_A(s ^ 1, v);
        }
        asm volatile("cp.async.wait_group 0;" ::: "memory");
        __syncthreads();
    }

    // ---- epilogue: bias + store NCHW + per-group GN partial sums ----
    float* ob = out + (size_t)b * COUT * NPIX;
#pragma unroll
    for (int j = 0; j < 8; j++) {
        int co = wn * 64 + j * 8 + 2 * tk;
        float b0 = sB[co], b1 = sB[co + 1];
        float s = 0.f, ss = 0.f;
#pragma unroll
        for (int i = 0; i < 2; i++) {
            int px = p0 + wm * 32 + i * 16 + ty;
            float v0 = acc[i][j][0] + b0;
            float v1 = acc[i][j][1] + b1;
            float v2 = acc[i][j][2] + b0;
            float v3 = acc[i][j][3] + b1;
            ob[(size_t)co * NPIX + px]           = v0;
            ob[(size_t)(co + 1) * NPIX + px]     = v1;
            ob[(size_t)co * NPIX + px + 8]       = v2;
            ob[(size_t)(co + 1) * NPIX + px + 8] = v3;
            s  += v0 + v1 + v2 + v3;
            ss += v0 * v0 + v1 * v1 + v2 * v2 + v3 * v3;
        }
#pragma unroll
        for (int o2 = 16; o2; o2 >>= 1) {
            s  += __shfl_down_sync(0xFFFFFFFFu, s, o2);
            ss += __shfl_down_sync(0xFFFFFFFFu, ss, o2);
        }
        if (lane == 0) sP[wm * 32 + wn * 8 + j] = make_float2(s, ss);
    }
    __syncthreads();
    if (tid < 32) {
        float2 q0 = sP[tid], q1 = sP[32 + tid];
        g_part[(b * 32 + tid) * 64 + tile] = make_float2(q0.x + q1.x, q0.y + q1.y);
    }
}

// ---------------------------------------------------------------------------
// GroupNorm(32) + ReLU: stats from precomputed partials, one normalize pass.
__global__ __launch_bounds__(256)
void k_gn(float* __restrict__ out,
          const float* __restrict__ gamma, const float* __restrict__ beta) {
    int b = blockIdx.x >> 5;
    int g = blockIdx.x & 31;
    int tid = threadIdx.x;
    __shared__ float2 sp[64];
    __shared__ float stats[2];
    if (tid < 64) sp[tid] = g_part[(b * 32 + g) * 64 + tid];
    __syncthreads();
    if (tid == 0) {
        float S = 0.f, SS = 0.f;
#pragma unroll
        for (int i = 0; i < 64; i++) { S += sp[i].x; SS += sp[i].y; }
        float mu  = S * (1.f / 32768.f);
        float var = SS * (1.f / 32768.f) - mu * mu;
        stats[0] = mu;
        stats[1] = rsqrtf(var + 1e-5f);
    }
    __syncthreads();
    float mu = stats[0], rstd = stats[1];
    float4* b4 = (float4*)(out + ((size_t)(b * COUT + g * 8)) * NPIX);
    for (int i = tid; i < 8192; i += 256) {
        int c = g * 8 + (i >> 10);
        float ga = gamma[c], be = beta[c];
        float4 v = b4[i];
        v.x = fmaxf((v.x - mu) * rstd * ga + be, 0.f);
        v.y = fmaxf((v.y - mu) * rstd * ga + be, 0.f);
        v.z = fmaxf((v.z - mu) * rstd * ga + be, 0.f);
        v.w = fmaxf((v.w - mu) * rstd * ga + be, 0.f);
        b4[i] = v;
    }
}

// ---------------------------------------------------------------------------
extern "C" void kernel_launch(void* const* d_in, const int* in_sizes, int n_in,
                              void* d_out, int out_size) {
    const float* x      = (const float*)d_in[0];
    const float* offset = (const float*)d_in[1];
    const float* mask   = (const float*)d_in[2];
    const float* weight = (const float*)d_in[3];
    const float* bias   = (const float*)d_in[4];
    const float* gamma  = (const float*)d_in[5];
    const float* beta   = (const float*)d_in[6];
    float* out = (float*)d_out;

    cudaFuncSetAttribute(k_conv, cudaFuncAttributeMaxDynamicSharedMemorySize, SMEM_DYN);

    k_prep_x<<<dim3(128, 8, 4), dim3(32, 8)>>>(x);
    k_prep_w<<<NCHUNK, 256>>>(weight);
    k_prep_params<<<576, 256>>>(offset, mask);
    k_conv<<<256, 256, SMEM_DYN>>>(bias, out);
    k_gn<<<128, 256>>>(out, gamma, beta);
}

// round 11
// speedup vs baseline: 1.5095x; 1.5095x over previous
#include <cuda_runtime.h>
#include <cuda_fp16.h>
#include <cstdint>

#define B_    4
#define CIN   256
#define HH    64
#define WW    64
#define COUT  256
#define K2    9
#define NPIX  4096
#define NCHUNK 36               // 4 ci64-chunks * 9 k2, order: c64 outer, k2 inner
#define RPITCH 160              // bytes per smem row: conflict-free LDS.64 (stride 8 banks)

// ---------------- scratch ----------------
__device__ __align__(16) __half   g_xh[B_ * NPIX * CIN];     // x NHWC fp16
__device__ __align__(16) __half   g_wh[NCHUNK * 256 * 64];   // W fp16: [ch][co256][k64 permuted]
__device__ __align__(16) int4     g_sidx[B_ * K2 * NPIX];    // corner bases in uint4 units (pix*32)
__device__ __align__(16) float4   g_swt [B_ * K2 * NPIX];
__device__ __align__(16) float2   g_part[B_ * 32 * 64];      // GN partials [(b*32+g)*64 + tile]

__device__ __forceinline__ uint32_t smem_u32(const void* p) {
    uint32_t a;
    asm("{ .reg .u64 t; cvta.to.shared.u64 t, %1; cvt.u32.u64 %0, t; }" : "=r"(a) : "l"(p));
    return a;
}
__device__ __forceinline__ void mma_f16(float* c, uint32_t a0, uint32_t a1,
                                        uint32_t a2, uint32_t a3,
                                        uint32_t b0, uint32_t b1) {
    asm volatile("mma.sync.aligned.m16n8k16.row.col.f32.f16.f16.f32 "
        "{%0,%1,%2,%3}, {%4,%5,%6,%7}, {%8,%9}, {%0,%1,%2,%3};"
        : "+f"(c[0]), "+f"(c[1]), "+f"(c[2]), "+f"(c[3])
        : "r"(a0), "r"(a1), "r"(a2), "r"(a3), "r"(b0), "r"(b1));
}

// ---------------------------------------------------------------------------
// Prep 1: x NCHW -> NHWC fp16
__global__ void k_prep_x(const float* __restrict__ x) {
    __shared__ float tile[32][33];
    int b = blockIdx.z, p0 = blockIdx.x * 32, c0 = blockIdx.y * 32;
    int tx = threadIdx.x, ty = threadIdx.y;
#pragma unroll
    for (int i = ty; i < 32; i += 8)
        tile[i][tx] = x[(b * CIN + c0 + i) * NPIX + p0 + tx];
    __syncthreads();
#pragma unroll
    for (int i = ty; i < 32; i += 8)
        g_xh[(b * NPIX + p0 + i) * CIN + c0 + tx] = __float2half_rn(tile[tx][i]);
}

// Prep 2: W -> fp16 chunks [ch = c64*9 + k2][co][k64], k permuted within each
// group of 16: pos 4t+{0,1,2,3} <- k {2t, 2t+1, 2t+8, 2t+9}. A uses the same
// permutation, so the GEMM is unchanged while each fragment is one LDS.64.
__global__ void k_prep_w(const float* __restrict__ w) {
    int ch  = blockIdx.x;
    int c64 = ch / 9, k2 = ch - c64 * 9;
    __half* dst = g_wh + ch * 16384;
    for (int e = threadIdx.x; e < 16384; e += 256) {
        int co = e >> 6, p = e & 63;
        int gp = p >> 4, r = p & 15, t = r >> 2, u = r & 3;
        int k = gp * 16 + 2 * t + (u & 1) + ((u & 2) ? 8 : 0);
        float v = w[(co * CIN + c64 * 64 + k) * K2 + k2];
        dst[co * 64 + p] = __float2half_rn(v);
    }
}

// Prep 3: sampling params (corner bases in uint4 units, folded weights)
__global__ void k_prep_params(const float* __restrict__ offset,
                              const float* __restrict__ mask) {
    int t = blockIdx.x * blockDim.x + threadIdx.x;
    int b  = t / (K2 * NPIX);
    int r  = t - b * (K2 * NPIX);
    int k2 = r >> 12;
    int p  = r & (NPIX - 1);
    int ho = p >> 6, wo = p & 63;
    int ky = k2 / 3, kx = k2 - ky * 3;

    float dy_off = offset[(b * 2 * K2 + 2 * k2    ) * NPIX + p];
    float dx_off = offset[(b * 2 * K2 + 2 * k2 + 1) * NPIX + p];
    float m      = mask  [(b * K2 + k2) * NPIX + p];

    float yf = (float)(ky + ho - 1) + dy_off;
    float xf = (float)(kx + wo - 1) + dx_off;
    float y0f = floorf(yf), x0f = floorf(xf);
    float dy = yf - y0f, dx = xf - x0f;
    int y0 = (int)y0f, x0 = (int)x0f;
    int y1 = y0 + 1,   x1 = x0 + 1;

    float w00 = (1.f - dy) * (1.f - dx) * m;
    float w01 = (1.f - dy) * dx * m;
    float w10 = dy * (1.f - dx) * m;
    float w11 = dy * dx * m;
    bool vy0 = (y0 >= 0) & (y0 < HH), vy1 = (y1 >= 0) & (y1 < HH);
    bool vx0 = (x0 >= 0) & (x0 < WW), vx1 = (x1 >= 0) & (x1 < WW);
    if (!(vy0 & vx0)) w00 = 0.f;
    if (!(vy0 & vx1)) w01 = 0.f;
    if (!(vy1 & vx0)) w10 = 0.f;
    if (!(vy1 & vx1)) w11 = 0.f;

    int y0c = min(max(y0, 0), HH - 1), y1c = min(max(y1, 0), HH - 1);
    int x0c = min(max(x0, 0), WW - 1), x1c = min(max(x1, 0), WW - 1);
    int base = b * NPIX;
    g_sidx[t] = make_int4((base + y0c * WW + x0c) * 32,
                          (base + y0c * WW + x1c) * 32,
                          (base + y1c * WW + x0c) * 32,
                          (base + y1c * WW + x1c) * 32);
    g_swt[t] = make_float4(w00, w01, w10, w11);
}

// ---------------------------------------------------------------------------
// Main: fp16 m16n8k16 implicit GEMM, fp32 accumulate + fused GN partial stats.
// CTA: 64px x 256co, K=2304 in 36 chunks of 64 (c64 outer, k2 inner).
// grid 256, block 256 (8 warps), warp tile 32px x 64co, 2 CTAs/SM.
// WARP-STAGGERED producers: warps 0-3 build chunk ch+1 BEFORE the mma section
// (their gather latency covered by warps 4-7's mma); warps 4-7 build AFTER
// (covered by warps 0-3 finishing mma). Monolithic mma loop preserved.
// ---------------------------------------------------------------------------
// bytes: A0 0 | A1 10240 | W0 20480 | W1 61440 | sB 102400 | sP 103424 | end 103936
#define SMEM_DYN 103936

__global__ __launch_bounds__(256, 2)
void k_conv(const float* __restrict__ bias, float* __restrict__ out) {
    extern __shared__ char dsm[];
    char*   A_s[2] = { dsm,         dsm + 10240 };
    char*   W_s[2] = { dsm + 20480, dsm + 61440 };
    float*  sB = (float*)(dsm + 102400);
    float2* sP = (float2*)(dsm + 103424);        // [2 wm][32 groups]

    int tid  = threadIdx.x;
    int b    = blockIdx.x >> 6;
    int tile = blockIdx.x & 63;
    int p0   = tile * 64;
    int warp = tid >> 5, lane = tid & 31;

    sB[tid] = bias[tid];

    // ---- per-thread mappings ----
    int ty = lane >> 2, tk = lane & 3;        // mma frag coords
    int wm = warp >> 2, wn = warp & 3;        // warp tile: px wm*32, co wn*64
    int pl_b = tid >> 2, q_b = tid & 3;       // A-build: pixel, k-group-of-16
    const uint4* Xh = (const uint4*)g_xh;

    float acc[2][8][4];
#pragma unroll
    for (int i = 0; i < 2; i++)
#pragma unroll
        for (int j = 0; j < 8; j++)
#pragma unroll
            for (int qq = 0; qq < 4; qq++) acc[i][j][qq] = 0.f;

    // ---- builders ----
    // Half the W copy: early warps (tid<128) cover lin 0..1023, late cover 1024..2047.
    auto build_W_half = [&](int ch, int s, int half) {
        const char* src = (const char*)(g_wh + ch * 16384);
        uint32_t dst = smem_u32(W_s[s]);
        int base = half ? (tid + 896) : tid;     // tid in [0,128) or [128,256)
#pragma unroll
        for (int i = 0; i < 8; i++) {
            int lin = base + i * 128;            // 0..1023 / 1024..2047
            int co = lin >> 3, seg = lin & 7;    // 16B segment of 128B row
            uint32_t d = dst + (uint32_t)(co * RPITCH + seg * 16);
            const char* gp = src + (size_t)lin * 16;
            asm volatile("cp.async.cg.shared.global [%0], [%1], 16;" :: "r"(d), "l"(gp));
        }
    };
    auto build_A = [&](int ch, int s) {
        int c64 = ch / 9, k2 = ch - c64 * 9;
        int t = (b * K2 + k2) * NPIX + p0 + pl_b;
        int4   o  = __ldg(&g_sidx[t]);
        float4 wt = __ldg(&g_swt[t]);
        int cio = c64 * 8 + 2 * q_b;             // uint4 offset within pixel row
        uint4 ua0 = __ldg(&Xh[o.x + cio]), ua1 = __ldg(&Xh[o.x + cio + 1]);
        uint4 ub0 = __ldg(&Xh[o.y + cio]), ub1 = __ldg(&Xh[o.y + cio + 1]);
        uint4 uc0 = __ldg(&Xh[o.z + cio]), uc1 = __ldg(&Xh[o.z + cio + 1]);
        uint4 ud0 = __ldg(&Xh[o.w + cio]), ud1 = __ldg(&Xh[o.w + cio + 1]);
        __half2 w00 = __float2half2_rn(wt.x);
        __half2 w01 = __float2half2_rn(wt.y);
        __half2 w10 = __float2half2_rn(wt.z);
        __half2 w11 = __float2half2_rn(wt.w);
        __half2 va[8], vb[8], vc[8], vd[8];
        *(uint4*)&va[0] = ua0; *(uint4*)&va[4] = ua1;
        *(uint4*)&vb[0] = ub0; *(uint4*)&vb[4] = ub1;
        *(uint4*)&vc[0] = uc0; *(uint4*)&vc[4] = uc1;
        *(uint4*)&vd[0] = ud0; *(uint4*)&vd[4] = ud1;
        __half2 v[8];
#pragma unroll
        for (int h = 0; h < 8; h++) {
            __half2 r = __hmul2(w00, va[h]);
            r = __hfma2(w01, vb[h], r);
            r = __hfma2(w10, vc[h], r);
            v[h] = __hfma2(w11, vd[h], r);
        }
        // permuted pack (half2 slots): out[2t]=v[t], out[2t+1]=v[t+4]
        const uint32_t* vv = (const uint32_t*)v;
        uint4 s1 = make_uint4(vv[0], vv[4], vv[1], vv[5]);
        uint4 s2 = make_uint4(vv[2], vv[6], vv[3], vv[7]);
        uint4* ab = (uint4*)(A_s[s] + pl_b * RPITCH + q_b * 32);
        ab[0] = s1;
        ab[1] = s2;
    };

    // ---- prologue: build chunk 0 (all warps) ----
    build_W_half(0, 0, warp < 4 ? 0 : 1);
    asm volatile("cp.async.commit_group;" ::: "memory");
    build_A(0, 0);
    asm volatile("cp.async.wait_group 0;" ::: "memory");
    __syncthreads();

    for (int ch = 0; ch < NCHUNK; ch++) {
        int s = ch & 1;
        bool has = (ch + 1 < NCHUNK);

        // ---- early producers: warps 0-3 build chunk ch+1 now ----
        if (has && warp < 4) {
            build_W_half(ch + 1, s ^ 1, 0);
            asm volatile("cp.async.commit_group;" ::: "memory");
            build_A(ch + 1, s ^ 1);
        }

        // ---- mma on buffer s: monolithic; every fragment is one LDS.64 ----
        const char* As = A_s[s] + (wm * 32 + ty) * RPITCH + tk * 8;
        const char* Ws = W_s[s] + (wn * 64 + ty) * RPITCH + tk * 8;
#pragma unroll
        for (int ks = 0; ks < 4; ks++) {
            uint2 alo[2], ahi[2], bv[8];
#pragma unroll
            for (int i = 0; i < 2; i++) {
                alo[i] = *(const uint2*)(As + i * (16 * RPITCH) + ks * 32);
                ahi[i] = *(const uint2*)(As + i * (16 * RPITCH) + 8 * RPITCH + ks * 32);
            }
#pragma unroll
            for (int j = 0; j < 8; j++)
                bv[j] = *(const uint2*)(Ws + j * (8 * RPITCH) + ks * 32);
#pragma unroll
            for (int i = 0; i < 2; i++)
#pragma unroll
                for (int j = 0; j < 8; j++)
                    mma_f16(acc[i][j], alo[i].x, ahi[i].x, alo[i].y, ahi[i].y,
                            bv[j].x, bv[j].y);
        }

        // ---- late producers: warps 4-7 build chunk ch+1 now ----
        if (has && warp >= 4) {
            build_W_half(ch + 1, s ^ 1, 1);
            asm volatile("cp.async.commit_group;" ::: "memory");
            build_A(ch + 1, s ^ 1);
        }
        asm volatile("cp.async.wait_group 0;" ::: "memory");
        __syncthreads();
    }

    // ---- epilogue: bias + store NCHW + per-group GN partial sums ----
    float* ob = out + (size_t)b * COUT * NPIX;
#pragma unroll
    for (int j = 0; j < 8; j++) {
        int co = wn * 64 + j * 8 + 2 * tk;
        float b0 = sB[co], b1 = sB[co + 1];
        float s = 0.f, ss = 0.f;
#pragma unroll
        for (int i = 0; i < 2; i++) {
            int px = p0 + wm * 32 + i * 16 + ty;
            float v0 = acc[i][j][0] + b0;
            float v1 = acc[i][j][1] + b1;
            float v2 = acc[i][j][2] + b0;
            float v3 = acc[i][j][3] + b1;
            ob[(size_t)co * NPIX + px]           = v0;
            ob[(size_t)(co + 1) * NPIX + px]     = v1;
            ob[(size_t)co * NPIX + px + 8]       = v2;
            ob[(size_t)(co + 1) * NPIX + px + 8] = v3;
            s  += v0 + v1 + v2 + v3;
            ss += v0 * v0 + v1 * v1 + v2 * v2 + v3 * v3;
        }
#pragma unroll
        for (int o2 = 16; o2; o2 >>= 1) {
            s  += __shfl_down_sync(0xFFFFFFFFu, s, o2);
            ss += __shfl_down_sync(0xFFFFFFFFu, ss, o2);
        }
        if (lane == 0) sP[wm * 32 + wn * 8 + j] = make_float2(s, ss);
    }
    __syncthreads();
    if (tid < 32) {
        float2 q0 = sP[tid], q1 = sP[32 + tid];
        g_part[(b * 32 + tid) * 64 + tile] = make_float2(q0.x + q1.x, q0.y + q1.y);
    }
}

// ---------------------------------------------------------------------------
// GroupNorm(32) + ReLU: stats from precomputed partials, one normalize pass.
__global__ __launch_bounds__(256)
void k_gn(float* __restrict__ out,
          const float* __restrict__ gamma, const float* __restrict__ beta) {
    int b = blockIdx.x >> 5;
    int g = blockIdx.x & 31;
    int tid = threadIdx.x;
    __shared__ float2 sp[64];
    __shared__ float stats[2];
    if (tid < 64) sp[tid] = g_part[(b * 32 + g) * 64 + tid];
    __syncthreads();
    if (tid == 0) {
        float S = 0.f, SS = 0.f;
#pragma unroll
        for (int i = 0; i < 64; i++) { S += sp[i].x; SS += sp[i].y; }
        float mu  = S * (1.f / 32768.f);
        float var = SS * (1.f / 32768.f) - mu * mu;
        stats[0] = mu;
        stats[1] = rsqrtf(var + 1e-5f);
    }
    __syncthreads();
    float mu = stats[0], rstd = stats[1];
    float4* b4 = (float4*)(out + ((size_t)(b * COUT + g * 8)) * NPIX);
    for (int i = tid; i < 8192; i += 256) {
        int c = g * 8 + (i >> 10);
        float ga = gamma[c], be = beta[c];
        float4 v = b4[i];
        v.x = fmaxf((v.x - mu) * rstd * ga + be, 0.f);
        v.y = fmaxf((v.y - mu) * rstd * ga + be, 0.f);
        v.z = fmaxf((v.z - mu) * rstd * ga + be, 0.f);
        v.w = fmaxf((v.w - mu) * rstd * ga + be, 0.f);
        b4[i] = v;
    }
}

// ---------------------------------------------------------------------------
extern "C" void kernel_launch(void* const* d_in, const int* in_sizes, int n_in,
                              void* d_out, int out_size) {
    const float* x      = (const float*)d_in[0];
    const float* offset = (const float*)d_in[1];
    const float* mask   = (const float*)d_in[2];
    const float* weight = (const float*)d_in[3];
    const float* bias   = (const float*)d_in[4];
    const float* gamma  = (const float*)d_in[5];
    const float* beta   = (const float*)d_in[6];
    float* out = (float*)d_out;

    cudaFuncSetAttribute(k_conv, cudaFuncAttributeMaxDynamicSharedMemorySize, SMEM_DYN);

    k_prep_x<<<dim3(128, 8, 4), dim3(32, 8)>>>(x);
    k_prep_w<<<NCHUNK, 256>>>(weight);
    k_prep_params<<<576, 256>>>(offset, mask);
    k_conv<<<256, 256, SMEM_DYN>>>(bias, out);
    k_gn<<<128, 256>>>(out, gamma, beta);
}

// round 12
// speedup vs baseline: 1.5707x; 1.0406x over previous
#include <cuda_runtime.h>
#include <cuda_fp16.h>
#include <cstdint>

#define B_    4
#define CIN   256
#define HH    64
#define WW    64
#define COUT  256
#define K2    9
#define NPIX  4096
#define NCHUNK 36               // 4 ci64-chunks * 9 k2, order: c64 outer, k2 inner
#define RPITCH 160              // bytes per smem row: conflict-free LDS.64

// ---------------- scratch ----------------
__device__ __align__(16) __half   g_xh[B_ * NPIX * CIN];     // x NHWC fp16
__device__ __align__(16) __half   g_wh[NCHUNK * 256 * 64];   // W fp16: [ch][co256][k64 permuted]
__device__ __align__(16) int4     g_sidx[B_ * K2 * NPIX];    // corner bases in uint4 units (pix*32)
__device__ __align__(16) float4   g_swt [B_ * K2 * NPIX];
__device__ __align__(16) float2   g_part[B_ * 32 * 64];      // GN partials [(b*32+g)*64 + tile]
__device__ unsigned               g_cnt;                     // monotonic grid-barrier counter

__device__ __forceinline__ uint32_t smem_u32(const void* p) {
    uint32_t a;
    asm("{ .reg .u64 t; cvta.to.shared.u64 t, %1; cvt.u32.u64 %0, t; }" : "=r"(a) : "l"(p));
    return a;
}
__device__ __forceinline__ void mma_f16(float* c, uint32_t a0, uint32_t a1,
                                        uint32_t a2, uint32_t a3,
                                        uint32_t b0, uint32_t b1) {
    asm volatile("mma.sync.aligned.m16n8k16.row.col.f32.f16.f16.f32 "
        "{%0,%1,%2,%3}, {%4,%5,%6,%7}, {%8,%9}, {%0,%1,%2,%3};"
        : "+f"(c[0]), "+f"(c[1]), "+f"(c[2]), "+f"(c[3])
        : "r"(a0), "r"(a1), "r"(a2), "r"(a3), "r"(b0), "r"(b1));
}

// ---------------------------------------------------------------------------
// Prep 1: x NCHW -> NHWC fp16
__global__ void k_prep_x(const float* __restrict__ x) {
    __shared__ float tile[32][33];
    int b = blockIdx.z, p0 = blockIdx.x * 32, c0 = blockIdx.y * 32;
    int tx = threadIdx.x, ty = threadIdx.y;
#pragma unroll
    for (int i = ty; i < 32; i += 8)
        tile[i][tx] = x[(b * CIN + c0 + i) * NPIX + p0 + tx];
    __syncthreads();
#pragma unroll
    for (int i = ty; i < 32; i += 8)
        g_xh[(b * NPIX + p0 + i) * CIN + c0 + tx] = __float2half_rn(tile[tx][i]);
}

// Prep 2 (fused): blocks [0,576) -> sampling params; [576,612) -> W chunks.
__global__ void k_prep_misc(const float* __restrict__ offset,
                            const float* __restrict__ mask,
                            const float* __restrict__ w) {
    if (blockIdx.x < 576) {
        int t = blockIdx.x * 256 + threadIdx.x;
        int b  = t / (K2 * NPIX);
        int r  = t - b * (K2 * NPIX);
        int k2 = r >> 12;
        int p  = r & (NPIX - 1);
        int ho = p >> 6, wo = p & 63;
        int ky = k2 / 3, kx = k2 - ky * 3;

        float dy_off = offset[(b * 2 * K2 + 2 * k2    ) * NPIX + p];
        float dx_off = offset[(b * 2 * K2 + 2 * k2 + 1) * NPIX + p];
        float m      = mask  [(b * K2 + k2) * NPIX + p];

        float yf = (float)(ky + ho - 1) + dy_off;
        float xf = (float)(kx + wo - 1) + dx_off;
        float y0f = floorf(yf), x0f = floorf(xf);
        float dy = yf - y0f, dx = xf - x0f;
        int y0 = (int)y0f, x0 = (int)x0f;
        int y1 = y0 + 1,   x1 = x0 + 1;

        float w00 = (1.f - dy) * (1.f - dx) * m;
        float w01 = (1.f - dy) * dx * m;
        float w10 = dy * (1.f - dx) * m;
        float w11 = dy * dx * m;
        bool vy0 = (y0 >= 0) & (y0 < HH), vy1 = (y1 >= 0) & (y1 < HH);
        bool vx0 = (x0 >= 0) & (x0 < WW), vx1 = (x1 >= 0) & (x1 < WW);
        if (!(vy0 & vx0)) w00 = 0.f;
        if (!(vy0 & vx1)) w01 = 0.f;
        if (!(vy1 & vx0)) w10 = 0.f;
        if (!(vy1 & vx1)) w11 = 0.f;

        int y0c = min(max(y0, 0), HH - 1), y1c = min(max(y1, 0), HH - 1);
        int x0c = min(max(x0, 0), WW - 1), x1c = min(max(x1, 0), WW - 1);
        int base = b * NPIX;
        g_sidx[t] = make_int4((base + y0c * WW + x0c) * 32,
                              (base + y0c * WW + x1c) * 32,
                              (base + y1c * WW + x0c) * 32,
                              (base + y1c * WW + x1c) * 32);
        g_swt[t] = make_float4(w00, w01, w10, w11);
    } else {
        int ch  = blockIdx.x - 576;
        int c64 = ch / 9, k2 = ch - c64 * 9;
        __half* dst = g_wh + ch * 16384;
        for (int e = threadIdx.x; e < 16384; e += 256) {
            int co = e >> 6, p = e & 63;
            int gp = p >> 4, r = p & 15, t = r >> 2, u = r & 3;
            int k = gp * 16 + 2 * t + (u & 1) + ((u & 2) ? 8 : 0);
            float v = w[(co * CIN + c64 * 64 + k) * K2 + k2];
            dst[co * 64 + p] = __float2half_rn(v);
        }
    }
}

// ---------------------------------------------------------------------------
// Main: fp16 m16n8k16 implicit GEMM + FULLY FUSED GroupNorm+ReLU.
// CTA: 64px x 256co, K=2304 in 36 chunks; grid 256 = single co-resident wave
// (148 SMs x 2 CTAs), so a monotonic-counter grid barrier between GN-partial
// production and stats consumption is deadlock-free and graph-replay-safe.
// Warp-staggered producers + monolithic mma loop (protected 88.8us structure).
// ---------------------------------------------------------------------------
// bytes: A0 0 | A1 10240 | W0 20480 | W1 61440 | sB 102400 | sP 103424 |
//        sG 103936 | sBe 104960 | sMR 105984 | end 106240
#define SMEM_DYN 106240

__global__ __launch_bounds__(256, 2)
void k_conv(const float* __restrict__ bias, float* __restrict__ out,
            const float* __restrict__ gamma, const float* __restrict__ beta) {
    extern __shared__ char dsm[];
    char*   A_s[2] = { dsm,         dsm + 10240 };
    char*   W_s[2] = { dsm + 20480, dsm + 61440 };
    float*  sB  = (float*)(dsm + 102400);
    float2* sP  = (float2*)(dsm + 103424);       // [2 wm][32 groups]
    float*  sG  = (float*)(dsm + 103936);
    float*  sBe = (float*)(dsm + 104960);
    float2* sMR = (float2*)(dsm + 105984);       // per-group (mu, rstd)

    int tid  = threadIdx.x;
    int b    = blockIdx.x >> 6;
    int tile = blockIdx.x & 63;
    int p0   = tile * 64;
    int warp = tid >> 5, lane = tid & 31;

    sB[tid]  = bias[tid];
    sG[tid]  = gamma[tid];
    sBe[tid] = beta[tid];

    // ---- per-thread mappings ----
    int ty = lane >> 2, tk = lane & 3;        // mma frag coords
    int wm = warp >> 2, wn = warp & 3;        // warp tile: px wm*32, co wn*64
    int pl_b = tid >> 2, q_b = tid & 3;       // A-build: pixel, k-group-of-16
    const uint4* Xh = (const uint4*)g_xh;

    float acc[2][8][4];
#pragma unroll
    for (int i = 0; i < 2; i++)
#pragma unroll
        for (int j = 0; j < 8; j++)
#pragma unroll
            for (int qq = 0; qq < 4; qq++) acc[i][j][qq] = 0.f;

    // ---- builders ----
    auto build_W_half = [&](int ch, int s, int half) {
        const char* src = (const char*)(g_wh + ch * 16384);
        uint32_t dst = smem_u32(W_s[s]);
        int base = half ? (tid + 896) : tid;     // tid in [0,128) or [128,256)
#pragma unroll
        for (int i = 0; i < 8; i++) {
            int lin = base + i * 128;            // 0..1023 / 1024..2047
            int co = lin >> 3, seg = lin & 7;    // 16B segment of 128B row
            uint32_t d = dst + (uint32_t)(co * RPITCH + seg * 16);
            const char* gp = src + (size_t)lin * 16;
            asm volatile("cp.async.cg.shared.global [%0], [%1], 16;" :: "r"(d), "l"(gp));
        }
    };
    auto build_A = [&](int ch, int s) {
        int c64 = ch / 9, k2 = ch - c64 * 9;
        int t = (b * K2 + k2) * NPIX + p0 + pl_b;
        int4   o  = __ldg(&g_sidx[t]);
        float4 wt = __ldg(&g_swt[t]);
        int cio = c64 * 8 + 2 * q_b;             // uint4 offset within pixel row
        uint4 ua0 = __ldg(&Xh[o.x + cio]), ua1 = __ldg(&Xh[o.x + cio + 1]);
        uint4 ub0 = __ldg(&Xh[o.y + cio]), ub1 = __ldg(&Xh[o.y + cio + 1]);
        uint4 uc0 = __ldg(&Xh[o.z + cio]), uc1 = __ldg(&Xh[o.z + cio + 1]);
        uint4 ud0 = __ldg(&Xh[o.w + cio]), ud1 = __ldg(&Xh[o.w + cio + 1]);
        __half2 w00 = __float2half2_rn(wt.x);
        __half2 w01 = __float2half2_rn(wt.y);
        __half2 w10 = __float2half2_rn(wt.z);
        __half2 w11 = __float2half2_rn(wt.w);
        __half2 va[8], vb[8], vc[8], vd[8];
        *(uint4*)&va[0] = ua0; *(uint4*)&va[4] = ua1;
        *(uint4*)&vb[0] = ub0; *(uint4*)&vb[4] = ub1;
        *(uint4*)&vc[0] = uc0; *(uint4*)&vc[4] = uc1;
        *(uint4*)&vd[0] = ud0; *(uint4*)&vd[4] = ud1;
        __half2 v[8];
#pragma unroll
        for (int h = 0; h < 8; h++) {
            __half2 r = __hmul2(w00, va[h]);
            r = __hfma2(w01, vb[h], r);
            r = __hfma2(w10, vc[h], r);
            v[h] = __hfma2(w11, vd[h], r);
        }
        const uint32_t* vv = (const uint32_t*)v;
        uint4 s1 = make_uint4(vv[0], vv[4], vv[1], vv[5]);
        uint4 s2 = make_uint4(vv[2], vv[6], vv[3], vv[7]);
        uint4* ab = (uint4*)(A_s[s] + pl_b * RPITCH + q_b * 32);
        ab[0] = s1;
        ab[1] = s2;
    };

    // ---- prologue: build chunk 0 (all warps) ----
    build_W_half(0, 0, warp < 4 ? 0 : 1);
    asm volatile("cp.async.commit_group;" ::: "memory");
    build_A(0, 0);
    asm volatile("cp.async.wait_group 0;" ::: "memory");
    __syncthreads();

    for (int ch = 0; ch < NCHUNK; ch++) {
        int s = ch & 1;
        bool has = (ch + 1 < NCHUNK);

        if (has && warp < 4) {
            build_W_half(ch + 1, s ^ 1, 0);
            asm volatile("cp.async.commit_group;" ::: "memory");
            build_A(ch + 1, s ^ 1);
        }

        // ---- mma on buffer s: monolithic; every fragment is one LDS.64 ----
        const char* As = A_s[s] + (wm * 32 + ty) * RPITCH + tk * 8;
        const char* Ws = W_s[s] + (wn * 64 + ty) * RPITCH + tk * 8;
#pragma unroll
        for (int ks = 0; ks < 4; ks++) {
            uint2 alo[2], ahi[2], bv[8];
#pragma unroll
            for (int i = 0; i < 2; i++) {
                alo[i] = *(const uint2*)(As + i * (16 * RPITCH) + ks * 32);
                ahi[i] = *(const uint2*)(As + i * (16 * RPITCH) + 8 * RPITCH + ks * 32);
            }
#pragma unroll
            for (int j = 0; j < 8; j++)
                bv[j] = *(const uint2*)(Ws + j * (8 * RPITCH) + ks * 32);
#pragma unroll
            for (int i = 0; i < 2; i++)
#pragma unroll
                for (int j = 0; j < 8; j++)
                    mma_f16(acc[i][j], alo[i].x, ahi[i].x, alo[i].y, ahi[i].y,
                            bv[j].x, bv[j].y);
        }

        if (has && warp >= 4) {
            build_W_half(ch + 1, s ^ 1, 1);
            asm volatile("cp.async.commit_group;" ::: "memory");
            build_A(ch + 1, s ^ 1);
        }
        asm volatile("cp.async.wait_group 0;" ::: "memory");
        __syncthreads();
    }

    // ---- epilogue phase 1: add bias in-reg, per-group partial sums ----
#pragma unroll
    for (int j = 0; j < 8; j++) {
        int co = wn * 64 + j * 8 + 2 * tk;
        float b0 = sB[co], b1 = sB[co + 1];
        float s = 0.f, ss = 0.f;
#pragma unroll
        for (int i = 0; i < 2; i++) {
            acc[i][j][0] += b0;
            acc[i][j][1] += b1;
            acc[i][j][2] += b0;
            acc[i][j][3] += b1;
            s  += acc[i][j][0] + acc[i][j][1] + acc[i][j][2] + acc[i][j][3];
            ss += acc[i][j][0] * acc[i][j][0] + acc[i][j][1] * acc[i][j][1]
                + acc[i][j][2] * acc[i][j][2] + acc[i][j][3] * acc[i][j][3];
        }
#pragma unroll
        for (int o2 = 16; o2; o2 >>= 1) {
            s  += __shfl_down_sync(0xFFFFFFFFu, s, o2);
            ss += __shfl_down_sync(0xFFFFFFFFu, ss, o2);
        }
        if (lane == 0) sP[wm * 32 + wn * 8 + j] = make_float2(s, ss);
    }
    __syncthreads();
    if (tid < 32) {
        float2 q0 = sP[tid], q1 = sP[32 + tid];
        g_part[(b * 32 + tid) * 64 + tile] = make_float2(q0.x + q1.x, q0.y + q1.y);
    }

    // ---- grid barrier (all 256 CTAs co-resident: 148 SMs x 2) ----
    __syncthreads();                       // CTA's g_part stores ordered before tid0
    if (tid == 0) {
        __threadfence();                   // release
        unsigned old = atomicAdd(&g_cnt, 1u);
        unsigned target = old - (old & 255u) + 256u;   // monotonic: replay-safe
        while (*(volatile unsigned*)&g_cnt < target) { }
        __threadfence();                   // acquire
    }
    __syncthreads();

    // ---- epilogue phase 2: reduce 64 tiles x 32 groups for batch b ----
    {
        float2 pp = make_float2(0.f, 0.f);
        const float2* gp = g_part + (b * 32 + (tid >> 3)) * 64 + (tid & 7) * 8;
#pragma unroll
        for (int k = 0; k < 8; k++) { pp.x += gp[k].x; pp.y += gp[k].y; }
#pragma unroll
        for (int o2 = 4; o2; o2 >>= 1) {
            pp.x += __shfl_down_sync(0xFFFFFFFFu, pp.x, o2, 8);
            pp.y += __shfl_down_sync(0xFFFFFFFFu, pp.y, o2, 8);
        }
        if ((lane & 7) == 0) {
            float mu  = pp.x * (1.f / 32768.f);
            float var = pp.y * (1.f / 32768.f) - mu * mu;
            sMR[tid >> 3] = make_float2(mu, rsqrtf(var + 1e-5f));
        }
    }
    __syncthreads();
    {   // per-channel scale/shift in place: out = v*scale + shift
        float2 mr = sMR[tid >> 3];
        float sc = mr.y * sG[tid];
        float sh = sBe[tid] - mr.x * sc;
        sG[tid]  = sc;
        sBe[tid] = sh;
    }
    __syncthreads();

    // ---- epilogue phase 3: GN+ReLU apply, single write of out ----
    float* ob = out + (size_t)b * COUT * NPIX;
#pragma unroll
    for (int j = 0; j < 8; j++) {
        int co = wn * 64 + j * 8 + 2 * tk;
        float sc0 = sG[co], sh0 = sBe[co];
        float sc1 = sG[co + 1], sh1 = sBe[co + 1];
#pragma unroll
        for (int i = 0; i < 2; i++) {
            int px = p0 + wm * 32 + i * 16 + ty;
            ob[(size_t)co * NPIX + px]           = fmaxf(acc[i][j][0] * sc0 + sh0, 0.f);
            ob[(size_t)(co + 1) * NPIX + px]     = fmaxf(acc[i][j][1] * sc1 + sh1, 0.f);
            ob[(size_t)co * NPIX + px + 8]       = fmaxf(acc[i][j][2] * sc0 + sh0, 0.f);
            ob[(size_t)(co + 1) * NPIX + px + 8] = fmaxf(acc[i][j][3] * sc1 + sh1, 0.f);
        }
    }
}

// ---------------------------------------------------------------------------
extern "C" void kernel_launch(void* const* d_in, const int* in_sizes, int n_in,
                              void* d_out, int out_size) {
    const float* x      = (const float*)d_in[0];
    const float* offset = (const float*)d_in[1];
    const float* mask   = (const float*)d_in[2];
    const float* weight = (const float*)d_in[3];
    const float* bias   = (const float*)d_in[4];
    const float* gamma  = (const float*)d_in[5];
    const float* beta   = (const float*)d_in[6];
    float* out = (float*)d_out;

    cudaFuncSetAttribute(k_conv, cudaFuncAttributeMaxDynamicSharedMemorySize, SMEM_DYN);

    k_prep_x<<<dim3(128, 8, 4), dim3(32, 8)>>>(x);
    k_prep_misc<<<612, 256>>>(offset, mask, weight);
    k_conv<<<256, 256, SMEM_DYN>>>(bias, out, gamma, beta);
}